// round 10
// baseline (speedup 1.0000x reference)
#include <cuda_runtime.h>
#include <cuda_bf16.h>

// ---------------- problem constants ----------------
#define BB    32
#define NNc   6
#define BN    192
#define INCH  768
#define FHc   4
#define FWc   6
#define PXc   24
#define OCH   105
#define DDc   41
#define CCc   64
#define KSP   4
#define KC    192
#define NXc   200
#define NYc   200
#define GRID_PER_B (CCc*NXc*NYc)            // 2,560,000
#define FINAL_ELEMS ((size_t)BB*GRID_PER_B) // 81,920,000
#define NPTS  (BN*DDc*PXc)                  // 188,928

// tiling for BEV accumulation: 2 ix-rows per tile
#define TROWS 2
#define TILES_PER_B (NXc/TROWS)             // 100
#define NTILES (BB*TILES_PER_B)             // 3200
#define BINCAP 6144                         // >= max 5904 points per batch
#define CELLPITCH 401                       // odd pitch: conflict-free both phases
#define TILE_FLOATS (CCc*CELLPITCH)         // 25664 floats = 102,656 B
#define WPITCH2 65                          // float2 pitch for dup'd weights

// f32x2 packed math (sm_103a FFMA2 path, PTX-only)
#define FMA_F32X2(d,a,b,c) \
    asm("fma.rn.f32x2 %0, %1, %2, %3;" : "=l"(d) : "l"(a), "l"(b), "l"(c))
#define PACKF2(d, lo, hi) \
    asm("mov.b64 %0, {%1, %2};" : "=l"(d) : "r"(__float_as_uint(lo)), "r"(__float_as_uint(hi)))

// ---------------- scratch ----------------
__device__ float g_part [KSP*BN*PXc*OCH];
__device__ float g_depth[BN*PXc*DDc];
__device__ float g_feat [BN*PXc*CCc];
__device__ int   g_bincnt[NTILES];
__device__ unsigned int g_bins[(size_t)NTILES*BINCAP];

// ---------------- kernel 1: 1x1 conv, K-split partial GEMM, f32x2 ----------------
__global__ __launch_bounds__(162) void k_conv(const float* __restrict__ x,
                                              const float* __restrict__ wmat) {
    const int bn = blockIdx.x >> 2;
    const int ks = blockIdx.x & 3;
    __shared__ float  xs[KC*PXc];          // 18.0 KB
    __shared__ float2 ws2[108*WPITCH2];    // 54.8 KB, (w,w) duplicated pairs
    const int tid = threadIdx.x;
    const int pxg = tid % 6;
    const int og  = tid / 6;

    const float4* xg = (const float4*)(x + (size_t)bn*INCH*PXc + (size_t)ks*KC*PXc);
    for (int i = tid; i < KC*PXc/4; i += 162) ((float4*)xs)[i] = xg[i];

    unsigned long long acc01[4], acc23[4];
    #pragma unroll
    for (int j = 0; j < 4; ++j) { acc01[j] = 0ULL; acc23[j] = 0ULL; }

    for (int sub = 0; sub < 3; ++sub) {
        __syncthreads();
        for (int i = tid; i < 108*16; i += 162) {
            int o  = i >> 4;
            int c4 = i & 15;
            float4 v = make_float4(0.f,0.f,0.f,0.f);
            if (o < OCH)
                v = *(const float4*)(wmat + (size_t)o*INCH + ks*KC + sub*64 + c4*4);
            float2* dst = &ws2[o*WPITCH2 + c4*4];
            dst[0] = make_float2(v.x, v.x);
            dst[1] = make_float2(v.y, v.y);
            dst[2] = make_float2(v.z, v.z);
            dst[3] = make_float2(v.w, v.w);
        }
        __syncthreads();
        #pragma unroll 4
        for (int c = 0; c < 64; ++c) {
            float4 xv = *(const float4*)&xs[(sub*64 + c)*PXc + pxg*4];
            unsigned long long x01, x23;
            PACKF2(x01, xv.x, xv.y);
            PACKF2(x23, xv.z, xv.w);
            #pragma unroll
            for (int j = 0; j < 4; ++j) {
                unsigned long long wd =
                    *(const unsigned long long*)&ws2[(og*4 + j)*WPITCH2 + c];
                FMA_F32X2(acc01[j], wd, x01, acc01[j]);
                FMA_F32X2(acc23[j], wd, x23, acc23[j]);
            }
        }
    }

    #pragma unroll
    for (int j = 0; j < 4; ++j) {
        int o = og*4 + j;
        if (o >= OCH) continue;
        float a0 = __uint_as_float((unsigned)(acc01[j] & 0xffffffffu));
        float a1 = __uint_as_float((unsigned)(acc01[j] >> 32));
        float a2 = __uint_as_float((unsigned)(acc23[j] & 0xffffffffu));
        float a3 = __uint_as_float((unsigned)(acc23[j] >> 32));
        size_t base = (((size_t)ks*BN + bn)*PXc + pxg*4)*OCH + o;
        g_part[base]          = a0;
        g_part[base +   OCH]  = a1;
        g_part[base + 2*OCH]  = a2;
        g_part[base + 3*OCH]  = a3;
    }
}

// ---------------- kernel 2: reduce + bias + softmax + split ----------------
__global__ __launch_bounds__(128) void k_softmax(const float* __restrict__ bias,
                                                 float* __restrict__ out_logit) {
    const int warp = threadIdx.x >> 5;
    const int lane = threadIdx.x & 31;
    const int pid  = blockIdx.x*4 + warp;
    const int bn   = pid / PXc;
    const int px   = pid % PXc;

    float y[4];
    #pragma unroll
    for (int k = 0; k < 4; ++k) {
        int id = lane + 32*k;
        float v = 0.0f;
        if (id < OCH) {
            v = bias[id];
            #pragma unroll
            for (int ks = 0; ks < KSP; ++ks)
                v += g_part[(((size_t)ks*BN + bn)*PXc + px)*OCH + id];
        }
        y[k] = v;
    }

    float m = y[0];
    if (lane < 9) m = fmaxf(m, y[1]);
    #pragma unroll
    for (int s = 16; s; s >>= 1) m = fmaxf(m, __shfl_xor_sync(0xffffffffu, m, s));
    float e0 = expf(y[0] - m);
    float e1 = (lane < 9) ? expf(y[1] - m) : 0.0f;
    float ssum = e0 + e1;
    #pragma unroll
    for (int s = 16; s; s >>= 1) ssum += __shfl_xor_sync(0xffffffffu, ssum, s);

    out_logit[((size_t)bn*DDc + lane)*PXc + px] = y[0];
    if (lane < 9) out_logit[((size_t)bn*DDc + lane + 32)*PXc + px] = y[1];

    size_t pbase = (size_t)(bn*PXc + px);
    g_depth[pbase*DDc + lane] = e0 / ssum;
    if (lane < 9) g_depth[pbase*DDc + lane + 32] = e1 / ssum;

    if (lane >= 9) g_feat[pbase*CCc + (lane + 32 - 41)] = y[1];
    g_feat[pbase*CCc + (lane + 64 - 41)] = y[2];
    if (lane < 9) g_feat[pbase*CCc + (lane + 96 - 41)] = y[3];
}

// ---------------- kernel 3: geometry (inline inverse) + warp-aggregated binning ----------------
__global__ __launch_bounds__(256) void k_bin(const float* __restrict__ rots,
                                             const float* __restrict__ intr,
                                             const float* __restrict__ trans) {
    const int p = blockIdx.x*256 + threadIdx.x;   // grid covers NPTS exactly

    const int bn = p / (DDc*PXc);
    const int r  = p % (DDc*PXc);
    const int d  = r / PXc;
    const int px = r % PXc;
    const int h  = px / FWc;
    const int w  = px % FWc;

    // frustum point (match numpy linspace exactly)
    const float dsv = 4.0f + (float)d;
    const float p0 = (float)((double)w * (199.0/5.0)) * dsv;
    const float p1 = (float)((double)h * (149.0/3.0)) * dsv;
    const float p2 = dsv;

    // inv(intrins) per thread (broadcast loads within warp)
    const float* K = intr + bn*9;
    float a=K[0],b=K[1],c=K[2],dd=K[3],e=K[4],f=K[5],g=K[6],hh=K[7],i=K[8];
    float A  =  (e*i - f*hh);
    float Bc = -(dd*i - f*g);
    float Cc =  (dd*hh - e*g);
    float idet = 1.0f/(a*A + b*Bc + c*Cc);
    // q = K^-1 * p
    float q0 = (A*p0          - (b*i-c*hh)*p1 + (b*f-c*e)*p2) * idet;
    float q1 = (Bc*p0         + (a*i-c*g)*p1  - (a*f-c*dd)*p2) * idet;
    float q2 = (Cc*p0         - (a*hh-b*g)*p1 + (a*e-b*dd)*p2) * idet;
    // g = R*q + T
    const float* R = rots  + bn*9;
    const float* T = trans + bn*3;
    float gx = R[0]*q0 + R[1]*q1 + R[2]*q2 + T[0];
    float gy = R[3]*q0 + R[4]*q1 + R[5]*q2 + T[1];
    float gz = R[6]*q0 + R[7]*q1 + R[8]*q2 + T[2];

    // truncation toward zero == .astype(int32)
    int ix = (int)((gx + 50.0f) / 0.5f);
    int iy = (int)((gy + 50.0f) / 0.5f);
    int iz = (int)((gz + 10.0f) / 20.0f);
    bool kept = (ix >= 0 && ix < NXc && iy >= 0 && iy < NYc && iz == 0);

    if (kept) {
        const int bidx = bn / NNc;
        const int tile = bidx*TILES_PER_B + (ix >> 1);
        const int cell = (ix & 1)*NYc + iy;
        const int pd   = (bn*PXc + px)*DDc + d;

        // warp-aggregated counter update
        unsigned peers  = __match_any_sync(__activemask(), tile);
        int      leader = __ffs(peers) - 1;
        int      lane   = threadIdx.x & 31;
        int      rank   = __popc(peers & ((1u << lane) - 1u));
        int base;
        if (lane == leader) base = atomicAdd(&g_bincnt[tile], __popc(peers));
        base = __shfl_sync(peers, base, leader);
        g_bins[(size_t)tile*BINCAP + base + rank] = ((unsigned)pd << 9) | (unsigned)cell;
    }
}

// ---------------- kernel 4: per-tile SMEM accumulate + full write-out ----------------
__global__ __launch_bounds__(1024) void k_tile(float* __restrict__ out) {
    extern __shared__ float s[];                    // [c*CELLPITCH + cell]
    const int tile = blockIdx.x;
    const int b    = tile / TILES_PER_B;
    const int tix  = tile % TILES_PER_B;
    const int tid  = threadIdx.x;
    const int lane = tid & 31;
    const int wid  = tid >> 5;

    // zero strip
    for (int i = tid; i < TILE_FLOATS/4; i += 1024)
        ((float4*)s)[i] = make_float4(0.f,0.f,0.f,0.f);
    __syncthreads();

    // accumulate (warp per record, lanes = channels; lane stride 401 -> conflict-free)
    const int cnt = g_bincnt[tile];
    const unsigned* rec = g_bins + (size_t)tile*BINCAP;
    for (int i = wid; i < cnt; i += 32) {
        unsigned e = rec[i];
        int cell = (int)(e & 511u);
        int pd   = (int)(e >> 9);
        float dep = g_depth[pd];
        int pb = pd / DDc;
        const float* fp = g_feat + (size_t)pb*CCc;
        float f0 = fp[lane];
        float f1 = fp[lane + 32];
        atomicAdd(&s[ lane      *CELLPITCH + cell], dep*f0);
        atomicAdd(&s[(lane + 32)*CELLPITCH + cell], dep*f1);
    }
    __syncthreads();

    // write full strip: lanes walk consecutive iy -> conflict-free LDS + coalesced STG
    for (int j = tid; j < TROWS*CCc*NYc; j += 1024) {
        int iy = j % NYc;
        int pr = j / NYc;          // 0..127
        int c  = pr >> 1;
        int row= pr & 1;
        float v = s[c*CELLPITCH + row*NYc + iy];
        out[((size_t)(b*CCc + c)*NXc + tix*TROWS + row)*NYc + iy] = v;
    }
}

// ---------------- launch ----------------
extern "C" void kernel_launch(void* const* d_in, const int* in_sizes, int n_in,
                              void* d_out, int out_size) {
    const float* x     = (const float*)d_in[0];
    const float* rots  = (const float*)d_in[1];
    const float* trans = (const float*)d_in[2];
    const float* intr  = (const float*)d_in[3];
    const float* cw    = (const float*)d_in[4];
    const float* cb    = (const float*)d_in[5];
    float* out = (float*)d_out;

    static void* bincnt_ptr = nullptr;
    if (!bincnt_ptr) {
        cudaFuncSetAttribute(k_tile, cudaFuncAttributeMaxDynamicSharedMemorySize,
                             TILE_FLOATS*sizeof(float));
        cudaGetSymbolAddress(&bincnt_ptr, g_bincnt);
    }

    cudaMemsetAsync(bincnt_ptr, 0, NTILES*sizeof(int), 0);
    k_conv   <<<BN*KSP, 162>>>(x, cw);
    k_softmax<<<(BN*PXc)/4, 128>>>(cb, out + FINAL_ELEMS);
    k_bin    <<<NPTS/256, 256>>>(rots, intr, trans);
    k_tile   <<<NTILES, 1024, TILE_FLOATS*sizeof(float)>>>(out);
}

// round 11
// speedup vs baseline: 1.2628x; 1.2628x over previous
#include <cuda_runtime.h>
#include <cuda_bf16.h>

// ---------------- problem constants ----------------
#define BB    32
#define NNc   6
#define BN    192
#define INCH  768
#define FHc   4
#define FWc   6
#define PXc   24
#define OCH   105
#define DDc   41
#define CCc   64
#define KSP   4
#define KC    192
#define NXc   200
#define NYc   200
#define GRID_PER_B (CCc*NXc*NYc)            // 2,560,000
#define FINAL_ELEMS ((size_t)BB*GRID_PER_B) // 81,920,000
#define NPTS  (BN*DDc*PXc)                  // 188,928

// tiling for BEV accumulation: 2 ix-rows per tile
#define TROWS 2
#define TILES_PER_B (NXc/TROWS)             // 100
#define NTILES (BB*TILES_PER_B)             // 3200
#define BINCAP 6144                         // >= max 5904 points per batch
#define CPAD 65                             // [cell*CPAD + c]: contiguous warp atomics,
                                            // and write-out stride 65 -> bank stride 1
#define TILE_FLOATS (TROWS*NYc*CPAD)        // 26000 floats = 104 KB

// ---------------- scratch ----------------
__device__ float g_part [KSP*BN*PXc*OCH];
__device__ float g_depth[BN*PXc*DDc];
__device__ float g_feat [BN*PXc*CCc];
__device__ int   g_bincnt[NTILES];
__device__ unsigned int g_bins[(size_t)NTILES*BINCAP];

// ---------------- kernel 1: 1x1 conv, K-split partial GEMM (R8-proven) ----------------
__global__ __launch_bounds__(162) void k_conv(const float* __restrict__ x,
                                              const float* __restrict__ wmat) {
    const int bn = blockIdx.x >> 2;
    const int ks = blockIdx.x & 3;
    __shared__ float xs[KC*PXc];     // 18.0 KB
    __shared__ float ws[108*69];     // 29.1 KB
    const int tid = threadIdx.x;
    const int pxg = tid % 6;
    const int og  = tid / 6;

    const float4* xg = (const float4*)(x + (size_t)bn*INCH*PXc + (size_t)ks*KC*PXc);
    for (int i = tid; i < KC*PXc/4; i += 162) ((float4*)xs)[i] = xg[i];

    float acc[4][4];
    #pragma unroll
    for (int j = 0; j < 4; ++j)
        #pragma unroll
        for (int i = 0; i < 4; ++i) acc[j][i] = 0.0f;

    for (int sub = 0; sub < 3; ++sub) {
        __syncthreads();
        for (int i = tid; i < 108*16; i += 162) {
            int o  = i >> 4;
            int c4 = i & 15;
            float4 v = make_float4(0.f,0.f,0.f,0.f);
            if (o < OCH)
                v = *(const float4*)(wmat + (size_t)o*INCH + ks*KC + sub*64 + c4*4);
            int base = o*69 + c4*4;
            ws[base+0]=v.x; ws[base+1]=v.y; ws[base+2]=v.z; ws[base+3]=v.w;
        }
        __syncthreads();
        #pragma unroll 4
        for (int c = 0; c < 64; ++c) {
            float4 xv = *(const float4*)&xs[(sub*64 + c)*PXc + pxg*4];
            #pragma unroll
            for (int j = 0; j < 4; ++j) {
                float wv = ws[(og*4 + j)*69 + c];
                acc[j][0] += wv*xv.x; acc[j][1] += wv*xv.y;
                acc[j][2] += wv*xv.z; acc[j][3] += wv*xv.w;
            }
        }
    }

    #pragma unroll
    for (int j = 0; j < 4; ++j) {
        int o = og*4 + j;
        if (o >= OCH) continue;
        #pragma unroll
        for (int i = 0; i < 4; ++i) {
            int px = pxg*4 + i;
            g_part[(( (size_t)ks*BN + bn)*PXc + px)*OCH + o] = acc[j][i];
        }
    }
}

// ---------------- kernel 2: reduce + bias + softmax + split ----------------
__global__ __launch_bounds__(128) void k_softmax(const float* __restrict__ bias,
                                                 float* __restrict__ out_logit) {
    const int warp = threadIdx.x >> 5;
    const int lane = threadIdx.x & 31;
    const int pid  = blockIdx.x*4 + warp;
    const int bn   = pid / PXc;
    const int px   = pid % PXc;

    float y[4];
    #pragma unroll
    for (int k = 0; k < 4; ++k) {
        int id = lane + 32*k;
        float v = 0.0f;
        if (id < OCH) {
            v = bias[id];
            #pragma unroll
            for (int ks = 0; ks < KSP; ++ks)
                v += g_part[(((size_t)ks*BN + bn)*PXc + px)*OCH + id];
        }
        y[k] = v;
    }

    float m = y[0];
    if (lane < 9) m = fmaxf(m, y[1]);
    #pragma unroll
    for (int s = 16; s; s >>= 1) m = fmaxf(m, __shfl_xor_sync(0xffffffffu, m, s));
    float e0 = expf(y[0] - m);
    float e1 = (lane < 9) ? expf(y[1] - m) : 0.0f;
    float ssum = e0 + e1;
    #pragma unroll
    for (int s = 16; s; s >>= 1) ssum += __shfl_xor_sync(0xffffffffu, ssum, s);

    out_logit[((size_t)bn*DDc + lane)*PXc + px] = y[0];
    if (lane < 9) out_logit[((size_t)bn*DDc + lane + 32)*PXc + px] = y[1];

    size_t pbase = (size_t)(bn*PXc + px);
    g_depth[pbase*DDc + lane] = e0 / ssum;
    if (lane < 9) g_depth[pbase*DDc + lane + 32] = e1 / ssum;

    if (lane >= 9) g_feat[pbase*CCc + (lane + 32 - 41)] = y[1];
    g_feat[pbase*CCc + (lane + 64 - 41)] = y[2];
    if (lane < 9) g_feat[pbase*CCc + (lane + 96 - 41)] = y[3];
}

// ---------------- kernel 3: geometry (inline inverse) + warp-aggregated binning ----------------
__global__ __launch_bounds__(256) void k_bin(const float* __restrict__ rots,
                                             const float* __restrict__ intr,
                                             const float* __restrict__ trans) {
    const int p = blockIdx.x*256 + threadIdx.x;   // grid covers NPTS exactly

    const int bn = p / (DDc*PXc);
    const int r  = p % (DDc*PXc);
    const int d  = r / PXc;
    const int px = r % PXc;
    const int h  = px / FWc;
    const int w  = px % FWc;

    // frustum point (match numpy linspace exactly)
    const float dsv = 4.0f + (float)d;
    const float p0 = (float)((double)w * (199.0/5.0)) * dsv;
    const float p1 = (float)((double)h * (149.0/3.0)) * dsv;
    const float p2 = dsv;

    // inv(intrins) per thread (broadcast loads within warp)
    const float* K = intr + bn*9;
    float a=K[0],b=K[1],c=K[2],dd=K[3],e=K[4],f=K[5],g=K[6],hh=K[7],i=K[8];
    float A  =  (e*i - f*hh);
    float Bc = -(dd*i - f*g);
    float Cc =  (dd*hh - e*g);
    float idet = 1.0f/(a*A + b*Bc + c*Cc);
    float q0 = (A*p0  - (b*i-c*hh)*p1 + (b*f-c*e)*p2)  * idet;
    float q1 = (Bc*p0 + (a*i-c*g)*p1  - (a*f-c*dd)*p2) * idet;
    float q2 = (Cc*p0 - (a*hh-b*g)*p1 + (a*e-b*dd)*p2) * idet;
    const float* R = rots  + bn*9;
    const float* T = trans + bn*3;
    float gx = R[0]*q0 + R[1]*q1 + R[2]*q2 + T[0];
    float gy = R[3]*q0 + R[4]*q1 + R[5]*q2 + T[1];
    float gz = R[6]*q0 + R[7]*q1 + R[8]*q2 + T[2];

    // truncation toward zero == .astype(int32)
    int ix = (int)((gx + 50.0f) / 0.5f);
    int iy = (int)((gy + 50.0f) / 0.5f);
    int iz = (int)((gz + 10.0f) / 20.0f);
    bool kept = (ix >= 0 && ix < NXc && iy >= 0 && iy < NYc && iz == 0);

    if (kept) {
        const int bidx = bn / NNc;
        const int tile = bidx*TILES_PER_B + (ix >> 1);
        const int cell = (ix & 1)*NYc + iy;
        const int pd   = (bn*PXc + px)*DDc + d;

        unsigned peers  = __match_any_sync(__activemask(), tile);
        int      leader = __ffs(peers) - 1;
        int      lane   = threadIdx.x & 31;
        int      rank   = __popc(peers & ((1u << lane) - 1u));
        int base;
        if (lane == leader) base = atomicAdd(&g_bincnt[tile], __popc(peers));
        base = __shfl_sync(peers, base, leader);
        g_bins[(size_t)tile*BINCAP + base + rank] = ((unsigned)pd << 9) | (unsigned)cell;
    }
}

// ---------------- kernel 4: per-tile SMEM accumulate + full write-out ----------------
// layout s[cell*CPAD + c]: atomic phase = contiguous 32-lane segments (fast ATOMS),
// write-out lane<->iy: LDS stride 65 words -> bank stride 1 (conflict-free), STG coalesced.
__global__ __launch_bounds__(1024) void k_tile(float* __restrict__ out) {
    extern __shared__ float s[];
    const int tile = blockIdx.x;
    const int b    = tile / TILES_PER_B;
    const int tix  = tile % TILES_PER_B;
    const int tid  = threadIdx.x;
    const int lane = tid & 31;
    const int wid  = tid >> 5;

    for (int i = tid; i < TILE_FLOATS/4; i += 1024)
        ((float4*)s)[i] = make_float4(0.f,0.f,0.f,0.f);
    __syncthreads();

    const int cnt = g_bincnt[tile];
    const unsigned* rec = g_bins + (size_t)tile*BINCAP;
    for (int i = wid; i < cnt; i += 32) {
        unsigned e = rec[i];
        int cell = (int)(e & 511u);
        int pd   = (int)(e >> 9);
        float dep = g_depth[pd];
        int pb = pd / DDc;
        const float* fp = g_feat + (size_t)pb*CCc;
        float f0 = fp[lane];
        float f1 = fp[lane + 32];
        atomicAdd(&s[cell*CPAD + lane],      dep*f0);
        atomicAdd(&s[cell*CPAD + lane + 32], dep*f1);
    }
    __syncthreads();

    // scalar write-out: j -> (c,row,iy), iy innermost
    for (int j = tid; j < TROWS*CCc*NYc; j += 1024) {
        int iy = j % NYc;
        int pr = j / NYc;            // 0..127
        int c  = pr & 63;
        int row= pr >> 6;
        float v = s[(row*NYc + iy)*CPAD + c];
        out[((size_t)(b*CCc + c)*NXc + tix*TROWS + row)*NYc + iy] = v;
    }
}

// ---------------- launch ----------------
extern "C" void kernel_launch(void* const* d_in, const int* in_sizes, int n_in,
                              void* d_out, int out_size) {
    const float* x     = (const float*)d_in[0];
    const float* rots  = (const float*)d_in[1];
    const float* trans = (const float*)d_in[2];
    const float* intr  = (const float*)d_in[3];
    const float* cw    = (const float*)d_in[4];
    const float* cb    = (const float*)d_in[5];
    float* out = (float*)d_out;

    static void* bincnt_ptr = nullptr;
    if (!bincnt_ptr) {
        cudaFuncSetAttribute(k_tile, cudaFuncAttributeMaxDynamicSharedMemorySize,
                             TILE_FLOATS*sizeof(float));
        cudaGetSymbolAddress(&bincnt_ptr, g_bincnt);
    }

    cudaMemsetAsync(bincnt_ptr, 0, NTILES*sizeof(int), 0);
    k_conv   <<<BN*KSP, 162>>>(x, cw);
    k_softmax<<<(BN*PXc)/4, 128>>>(cb, out + FINAL_ELEMS);
    k_bin    <<<NPTS/256, 256>>>(rots, intr, trans);
    k_tile   <<<NTILES, 1024, TILE_FLOATS*sizeof(float)>>>(out);
}

// round 13
// speedup vs baseline: 1.7619x; 1.3952x over previous
#include <cuda_runtime.h>
#include <cuda_bf16.h>

// ---------------- problem constants ----------------
#define BB    32
#define NNc   6
#define BN    192
#define INCH  768
#define FHc   4
#define FWc   6
#define PXc   24
#define OCH   105
#define DDc   41
#define CCc   64
#define KSP   4
#define KC    192
#define NXc   200
#define NYc   200
#define GRID_PER_B (CCc*NXc*NYc)            // 2,560,000
#define FINAL_ELEMS ((size_t)BB*GRID_PER_B) // 81,920,000
#define NPTS  (BN*DDc*PXc)                  // 188,928

// tiling for BEV accumulation: 2 ix-rows per tile
#define TROWS 2
#define TILES_PER_B (NXc/TROWS)             // 100
#define NTILES (BB*TILES_PER_B)             // 3200
#define BINCAP 6144                         // >= max 5904 points per batch
#define CPAD 65                             // [cell*CPAD + c]: contiguous warp atomics,
                                            // write-out lane stride 65 -> bank stride 1
#define TILE_FLOATS (TROWS*NYc*CPAD)        // 26000 floats = 104 KB

// ---------------- scratch ----------------
__device__ float g_part [KSP*BN*PXc*OCH];
__device__ float g_depth[BN*PXc*DDc];
__device__ float g_feat [BN*PXc*CCc];
__device__ int   g_bincnt[NTILES];
__device__ unsigned int g_bins[(size_t)NTILES*BINCAP];

// ---------------- kernel 1: 1x1 conv, K-split partial GEMM (R8-proven) ----------------
__global__ __launch_bounds__(162) void k_conv(const float* __restrict__ x,
                                              const float* __restrict__ wmat) {
    const int bn = blockIdx.x >> 2;
    const int ks = blockIdx.x & 3;
    __shared__ float xs[KC*PXc];     // 18.0 KB
    __shared__ float ws[108*69];     // 29.1 KB
    const int tid = threadIdx.x;
    const int pxg = tid % 6;
    const int og  = tid / 6;

    const float4* xg = (const float4*)(x + (size_t)bn*INCH*PXc + (size_t)ks*KC*PXc);
    for (int i = tid; i < KC*PXc/4; i += 162) ((float4*)xs)[i] = xg[i];

    float acc[4][4];
    #pragma unroll
    for (int j = 0; j < 4; ++j)
        #pragma unroll
        for (int i = 0; i < 4; ++i) acc[j][i] = 0.0f;

    for (int sub = 0; sub < 3; ++sub) {
        __syncthreads();
        for (int i = tid; i < 108*16; i += 162) {
            int o  = i >> 4;
            int c4 = i & 15;
            float4 v = make_float4(0.f,0.f,0.f,0.f);
            if (o < OCH)
                v = *(const float4*)(wmat + (size_t)o*INCH + ks*KC + sub*64 + c4*4);
            int base = o*69 + c4*4;
            ws[base+0]=v.x; ws[base+1]=v.y; ws[base+2]=v.z; ws[base+3]=v.w;
        }
        __syncthreads();
        #pragma unroll 4
        for (int c = 0; c < 64; ++c) {
            float4 xv = *(const float4*)&xs[(sub*64 + c)*PXc + pxg*4];
            #pragma unroll
            for (int j = 0; j < 4; ++j) {
                float wv = ws[(og*4 + j)*69 + c];
                acc[j][0] += wv*xv.x; acc[j][1] += wv*xv.y;
                acc[j][2] += wv*xv.z; acc[j][3] += wv*xv.w;
            }
        }
    }

    #pragma unroll
    for (int j = 0; j < 4; ++j) {
        int o = og*4 + j;
        if (o >= OCH) continue;
        #pragma unroll
        for (int i = 0; i < 4; ++i) {
            int px = pxg*4 + i;
            g_part[(( (size_t)ks*BN + bn)*PXc + px)*OCH + o] = acc[j][i];
        }
    }
}

// ---------------- kernel 2: reduce + bias + softmax + split ----------------
__global__ __launch_bounds__(128) void k_softmax(const float* __restrict__ bias,
                                                 float* __restrict__ out_logit) {
    const int warp = threadIdx.x >> 5;
    const int lane = threadIdx.x & 31;
    const int pid  = blockIdx.x*4 + warp;
    const int bn   = pid / PXc;
    const int px   = pid % PXc;

    float y[4];
    #pragma unroll
    for (int k = 0; k < 4; ++k) {
        int id = lane + 32*k;
        float v = 0.0f;
        if (id < OCH) {
            v = bias[id];
            #pragma unroll
            for (int ks = 0; ks < KSP; ++ks)
                v += g_part[(((size_t)ks*BN + bn)*PXc + px)*OCH + id];
        }
        y[k] = v;
    }

    float m = y[0];
    if (lane < 9) m = fmaxf(m, y[1]);
    #pragma unroll
    for (int s = 16; s; s >>= 1) m = fmaxf(m, __shfl_xor_sync(0xffffffffu, m, s));
    float e0 = expf(y[0] - m);
    float e1 = (lane < 9) ? expf(y[1] - m) : 0.0f;
    float ssum = e0 + e1;
    #pragma unroll
    for (int s = 16; s; s >>= 1) ssum += __shfl_xor_sync(0xffffffffu, ssum, s);

    out_logit[((size_t)bn*DDc + lane)*PXc + px] = y[0];
    if (lane < 9) out_logit[((size_t)bn*DDc + lane + 32)*PXc + px] = y[1];

    size_t pbase = (size_t)(bn*PXc + px);
    g_depth[pbase*DDc + lane] = e0 / ssum;
    if (lane < 9) g_depth[pbase*DDc + lane + 32] = e1 / ssum;

    if (lane >= 9) g_feat[pbase*CCc + (lane + 32 - 41)] = y[1];
    g_feat[pbase*CCc + (lane + 64 - 41)] = y[2];
    if (lane < 9) g_feat[pbase*CCc + (lane + 96 - 41)] = y[3];
}

// ---------------- kernel 3: geometry (inline inverse) + warp-aggregated binning ----------------
__global__ __launch_bounds__(256) void k_bin(const float* __restrict__ rots,
                                             const float* __restrict__ intr,
                                             const float* __restrict__ trans) {
    const int p = blockIdx.x*256 + threadIdx.x;   // grid covers NPTS exactly

    const int bn = p / (DDc*PXc);
    const int r  = p % (DDc*PXc);
    const int d  = r / PXc;
    const int px = r % PXc;
    const int h  = px / FWc;
    const int w  = px % FWc;

    // frustum point (match numpy linspace exactly)
    const float dsv = 4.0f + (float)d;
    const float p0 = (float)((double)w * (199.0/5.0)) * dsv;
    const float p1 = (float)((double)h * (149.0/3.0)) * dsv;
    const float p2 = dsv;

    // inv(intrins) per thread (broadcast loads within warp)
    const float* K = intr + bn*9;
    float a=K[0],b=K[1],c=K[2],dd=K[3],e=K[4],f=K[5],g=K[6],hh=K[7],i=K[8];
    float A  =  (e*i - f*hh);
    float Bc = -(dd*i - f*g);
    float Cc =  (dd*hh - e*g);
    float idet = 1.0f/(a*A + b*Bc + c*Cc);
    float q0 = (A*p0  - (b*i-c*hh)*p1 + (b*f-c*e)*p2)  * idet;
    float q1 = (Bc*p0 + (a*i-c*g)*p1  - (a*f-c*dd)*p2) * idet;
    float q2 = (Cc*p0 - (a*hh-b*g)*p1 + (a*e-b*dd)*p2) * idet;
    const float* R = rots  + bn*9;
    const float* T = trans + bn*3;
    float gx = R[0]*q0 + R[1]*q1 + R[2]*q2 + T[0];
    float gy = R[3]*q0 + R[4]*q1 + R[5]*q2 + T[1];
    float gz = R[6]*q0 + R[7]*q1 + R[8]*q2 + T[2];

    // truncation toward zero == .astype(int32)
    int ix = (int)((gx + 50.0f) / 0.5f);
    int iy = (int)((gy + 50.0f) / 0.5f);
    int iz = (int)((gz + 10.0f) / 20.0f);
    bool kept = (ix >= 0 && ix < NXc && iy >= 0 && iy < NYc && iz == 0);

    if (kept) {
        const int bidx = bn / NNc;
        const int tile = bidx*TILES_PER_B + (ix >> 1);
        const int cell = (ix & 1)*NYc + iy;
        const int pb   = bn*PXc + px;                // 13 bits

        unsigned peers  = __match_any_sync(__activemask(), tile);
        int      leader = __ffs(peers) - 1;
        int      lane   = threadIdx.x & 31;
        int      rank   = __popc(peers & ((1u << lane) - 1u));
        int base;
        if (lane == leader) base = atomicAdd(&g_bincnt[tile], __popc(peers));
        base = __shfl_sync(peers, base, leader);
        // record: pb[27:15] | d[14:9] | cell[8:0]  (no divide needed on read)
        g_bins[(size_t)tile*BINCAP + base + rank] =
            ((unsigned)pb << 15) | ((unsigned)d << 9) | (unsigned)cell;
    }
}

// ---------------- kernel 4: per-tile SMEM accumulate + full write-out ----------------
__global__ __launch_bounds__(1024) void k_tile(float* __restrict__ out) {
    extern __shared__ float s[];
    const int tile = blockIdx.x;
    const int b    = tile / TILES_PER_B;
    const int tix  = tile % TILES_PER_B;
    const int tid  = threadIdx.x;
    const int lane = tid & 31;
    const int wid  = tid >> 5;

    for (int i = tid; i < TILE_FLOATS/4; i += 1024)
        ((float4*)s)[i] = make_float4(0.f,0.f,0.f,0.f);
    __syncthreads();

    // accumulate: contiguous warp atomics, no divides (record carries pb,d)
    const int cnt = g_bincnt[tile];
    const unsigned* rec = g_bins + (size_t)tile*BINCAP;
    for (int i = wid; i < cnt; i += 32) {
        unsigned e = rec[i];
        int cell = (int)(e & 511u);
        int d    = (int)((e >> 9) & 63u);
        int pb   = (int)(e >> 15);
        float dep = g_depth[pb*DDc + d];
        const float* fp = g_feat + (size_t)pb*CCc;
        float f0 = fp[lane];
        float f1 = fp[lane + 32];
        atomicAdd(&s[cell*CPAD + lane],      dep*f0);
        atomicAdd(&s[cell*CPAD + lane + 32], dep*f1);
    }
    __syncthreads();

    // write-out: lanes walk consecutive iy (conflict-free LDS, coalesced STG),
    // additive carry stepping instead of per-iter div/mod (1024 = 5*200 + 24)
    {
        int iy = tid % NYc;          // one-time division
        int pr = tid / NYc;          // 0..5
        const size_t outb = (size_t)b*CCc*NXc*NYc + (size_t)(tix*TROWS)*NYc;
        #pragma unroll 5
        for (int it = 0; it < 25; ++it) {
            int c   = pr & 63;
            int row = pr >> 6;
            out[outb + ((size_t)c*NXc + row)*NYc + iy] = s[(row*NYc + iy)*CPAD + c];
            iy += 24; pr += 5;
            if (iy >= NYc) { iy -= NYc; pr += 1; }
        }
    }
}

// ---------------- launch ----------------
extern "C" void kernel_launch(void* const* d_in, const int* in_sizes, int n_in,
                              void* d_out, int out_size) {
    const float* x     = (const float*)d_in[0];
    const float* rots  = (const float*)d_in[1];
    const float* trans = (const float*)d_in[2];
    const float* intr  = (const float*)d_in[3];
    const float* cw    = (const float*)d_in[4];
    const float* cb    = (const float*)d_in[5];
    float* out = (float*)d_out;

    static void* bincnt_ptr = nullptr;
    if (!bincnt_ptr) {
        cudaFuncSetAttribute(k_tile, cudaFuncAttributeMaxDynamicSharedMemorySize,
                             TILE_FLOATS*sizeof(float));
        cudaGetSymbolAddress(&bincnt_ptr, g_bincnt);
    }

    cudaMemsetAsync(bincnt_ptr, 0, NTILES*sizeof(int), 0);
    k_conv   <<<BN*KSP, 162>>>(x, cw);
    k_softmax<<<(BN*PXc)/4, 128>>>(cb, out + FINAL_ELEMS);
    k_bin    <<<NPTS/256, 256>>>(rots, intr, trans);
    k_tile   <<<NTILES, 1024, TILE_FLOATS*sizeof(float)>>>(out);
}

// round 14
// speedup vs baseline: 1.9590x; 1.1119x over previous
#include <cuda_runtime.h>
#include <cuda_bf16.h>

// ---------------- problem constants ----------------
#define BB    32
#define NNc   6
#define BN    192
#define INCH  768
#define FHc   4
#define FWc   6
#define PXc   24
#define OCH   105
#define DDc   41
#define CCc   64
#define KSP   4
#define KC    192
#define NXc   200
#define NYc   200
#define GRID_PER_B (CCc*NXc*NYc)            // 2,560,000
#define FINAL_ELEMS ((size_t)BB*GRID_PER_B) // 81,920,000
#define NPTS  (BN*DDc*PXc)                  // 188,928

// tiling for BEV accumulation: 2 ix-rows per tile
#define TROWS 2
#define TILES_PER_B (NXc/TROWS)             // 100
#define NTILES (BB*TILES_PER_B)             // 3200
#define BINCAP 6144                         // >= max 5904 points per batch
#define CPAD 65                             // [cell*CPAD + c]: contiguous warp atomics,
                                            // write-out lane stride 65 -> bank stride 1
#define TILE_FLOATS (TROWS*NYc*CPAD)        // 26000 floats = 104 KB

// ---------------- scratch ----------------
__device__ float g_part [KSP*BN*PXc*OCH];
__device__ float g_depth[BN*PXc*DDc];
__device__ float g_feat [BN*PXc*CCc];
__device__ int   g_bincnt[NTILES];
__device__ unsigned int g_bins[(size_t)NTILES*BINCAP];

// ---------------- kernel 1: 1x1 conv, K-split partial GEMM (R8-proven) ----------------
__global__ __launch_bounds__(162) void k_conv(const float* __restrict__ x,
                                              const float* __restrict__ wmat) {
    const int bn = blockIdx.x >> 2;
    const int ks = blockIdx.x & 3;
    __shared__ float xs[KC*PXc];     // 18.0 KB
    __shared__ float ws[108*69];     // 29.1 KB
    const int tid = threadIdx.x;
    const int pxg = tid % 6;
    const int og  = tid / 6;

    const float4* xg = (const float4*)(x + (size_t)bn*INCH*PXc + (size_t)ks*KC*PXc);
    for (int i = tid; i < KC*PXc/4; i += 162) ((float4*)xs)[i] = xg[i];

    float acc[4][4];
    #pragma unroll
    for (int j = 0; j < 4; ++j)
        #pragma unroll
        for (int i = 0; i < 4; ++i) acc[j][i] = 0.0f;

    for (int sub = 0; sub < 3; ++sub) {
        __syncthreads();
        for (int i = tid; i < 108*16; i += 162) {
            int o  = i >> 4;
            int c4 = i & 15;
            float4 v = make_float4(0.f,0.f,0.f,0.f);
            if (o < OCH)
                v = *(const float4*)(wmat + (size_t)o*INCH + ks*KC + sub*64 + c4*4);
            int base = o*69 + c4*4;
            ws[base+0]=v.x; ws[base+1]=v.y; ws[base+2]=v.z; ws[base+3]=v.w;
        }
        __syncthreads();
        #pragma unroll 4
        for (int c = 0; c < 64; ++c) {
            float4 xv = *(const float4*)&xs[(sub*64 + c)*PXc + pxg*4];
            #pragma unroll
            for (int j = 0; j < 4; ++j) {
                float wv = ws[(og*4 + j)*69 + c];
                acc[j][0] += wv*xv.x; acc[j][1] += wv*xv.y;
                acc[j][2] += wv*xv.z; acc[j][3] += wv*xv.w;
            }
        }
    }

    #pragma unroll
    for (int j = 0; j < 4; ++j) {
        int o = og*4 + j;
        if (o >= OCH) continue;
        #pragma unroll
        for (int i = 0; i < 4; ++i) {
            int px = pxg*4 + i;
            g_part[(( (size_t)ks*BN + bn)*PXc + px)*OCH + o] = acc[j][i];
        }
    }
}

// ---------------- kernel 2: reduce + bias + softmax + split ----------------
__global__ __launch_bounds__(128) void k_softmax(const float* __restrict__ bias,
                                                 float* __restrict__ out_logit) {
    const int warp = threadIdx.x >> 5;
    const int lane = threadIdx.x & 31;
    const int pid  = blockIdx.x*4 + warp;
    const int bn   = pid / PXc;
    const int px   = pid % PXc;

    float y[4];
    #pragma unroll
    for (int k = 0; k < 4; ++k) {
        int id = lane + 32*k;
        float v = 0.0f;
        if (id < OCH) {
            v = bias[id];
            #pragma unroll
            for (int ks = 0; ks < KSP; ++ks)
                v += g_part[(((size_t)ks*BN + bn)*PXc + px)*OCH + id];
        }
        y[k] = v;
    }

    float m = y[0];
    if (lane < 9) m = fmaxf(m, y[1]);
    #pragma unroll
    for (int s = 16; s; s >>= 1) m = fmaxf(m, __shfl_xor_sync(0xffffffffu, m, s));
    float e0 = expf(y[0] - m);
    float e1 = (lane < 9) ? expf(y[1] - m) : 0.0f;
    float ssum = e0 + e1;
    #pragma unroll
    for (int s = 16; s; s >>= 1) ssum += __shfl_xor_sync(0xffffffffu, ssum, s);

    out_logit[((size_t)bn*DDc + lane)*PXc + px] = y[0];
    if (lane < 9) out_logit[((size_t)bn*DDc + lane + 32)*PXc + px] = y[1];

    size_t pbase = (size_t)(bn*PXc + px);
    g_depth[pbase*DDc + lane] = e0 / ssum;
    if (lane < 9) g_depth[pbase*DDc + lane + 32] = e1 / ssum;

    if (lane >= 9) g_feat[pbase*CCc + (lane + 32 - 41)] = y[1];
    g_feat[pbase*CCc + (lane + 64 - 41)] = y[2];
    if (lane < 9) g_feat[pbase*CCc + (lane + 96 - 41)] = y[3];
}

// ---------------- kernel 3: geometry (inline inverse) + warp-aggregated binning ----------------
__global__ __launch_bounds__(256) void k_bin(const float* __restrict__ rots,
                                             const float* __restrict__ intr,
                                             const float* __restrict__ trans) {
    const int p = blockIdx.x*256 + threadIdx.x;

    const int bn = p / (DDc*PXc);
    const int r  = p % (DDc*PXc);
    const int d  = r / PXc;
    const int px = r % PXc;
    const int h  = px / FWc;
    const int w  = px % FWc;

    const float dsv = 4.0f + (float)d;
    const float p0 = (float)((double)w * (199.0/5.0)) * dsv;
    const float p1 = (float)((double)h * (149.0/3.0)) * dsv;
    const float p2 = dsv;

    const float* K = intr + bn*9;
    float a=K[0],b=K[1],c=K[2],dd=K[3],e=K[4],f=K[5],g=K[6],hh=K[7],i=K[8];
    float A  =  (e*i - f*hh);
    float Bc = -(dd*i - f*g);
    float Cc =  (dd*hh - e*g);
    float idet = 1.0f/(a*A + b*Bc + c*Cc);
    float q0 = (A*p0  - (b*i-c*hh)*p1 + (b*f-c*e)*p2)  * idet;
    float q1 = (Bc*p0 + (a*i-c*g)*p1  - (a*f-c*dd)*p2) * idet;
    float q2 = (Cc*p0 - (a*hh-b*g)*p1 + (a*e-b*dd)*p2) * idet;
    const float* R = rots  + bn*9;
    const float* T = trans + bn*3;
    float gx = R[0]*q0 + R[1]*q1 + R[2]*q2 + T[0];
    float gy = R[3]*q0 + R[4]*q1 + R[5]*q2 + T[1];
    float gz = R[6]*q0 + R[7]*q1 + R[8]*q2 + T[2];

    // truncation toward zero == .astype(int32)
    int ix = (int)((gx + 50.0f) / 0.5f);
    int iy = (int)((gy + 50.0f) / 0.5f);
    int iz = (int)((gz + 10.0f) / 20.0f);
    bool kept = (ix >= 0 && ix < NXc && iy >= 0 && iy < NYc && iz == 0);

    if (kept) {
        const int bidx = bn / NNc;
        const int tile = bidx*TILES_PER_B + (ix >> 1);
        const int cell = (ix & 1)*NYc + iy;
        const int pb   = bn*PXc + px;

        unsigned peers  = __match_any_sync(__activemask(), tile);
        int      leader = __ffs(peers) - 1;
        int      lane   = threadIdx.x & 31;
        int      rank   = __popc(peers & ((1u << lane) - 1u));
        int base;
        if (lane == leader) base = atomicAdd(&g_bincnt[tile], __popc(peers));
        base = __shfl_sync(peers, base, leader);
        g_bins[(size_t)tile*BINCAP + base + rank] =
            ((unsigned)pb << 15) | ((unsigned)d << 9) | (unsigned)cell;
    }
}

// ---------------- kernel 4: per-tile SMEM accumulate + full write-out ----------------
__global__ __launch_bounds__(1024) void k_tile(float* __restrict__ out) {
    extern __shared__ float s[];
    const int tile = blockIdx.x;
    const int b    = tile / TILES_PER_B;
    const int tix  = tile % TILES_PER_B;
    const int tid  = threadIdx.x;
    const int lane = tid & 31;
    const int wid  = tid >> 5;

    const int cnt = g_bincnt[tile];       // broadcast load

    // ---- empty tile: pure float4 zero store, no SMEM at all ----
    if (cnt == 0) {
        const float4 z = make_float4(0.f,0.f,0.f,0.f);
        #pragma unroll
        for (int pp = 0; pp < 4; ++pp) {
            int pr  = wid*4 + pp;          // 0..127
            int c   = pr >> 1;
            int row = pr & 1;
            float4* op = (float4*)(out + (size_t)b*GRID_PER_B
                                   + ((size_t)c*NXc + tix*TROWS + row)*NYc) + lane;
            op[0] = z;
            if (lane < 18) op[32] = z;     // 50 = 32 + 18 float4 per row
        }
        return;
    }

    // ---- zero strip ----
    for (int i = tid; i < TILE_FLOATS/4; i += 1024)
        ((float4*)s)[i] = make_float4(0.f,0.f,0.f,0.f);
    __syncthreads();

    // ---- accumulate: contiguous warp atomics, no divides ----
    const unsigned* rec = g_bins + (size_t)tile*BINCAP;
    for (int i = wid; i < cnt; i += 32) {
        unsigned e = rec[i];
        int cell = (int)(e & 511u);
        int d    = (int)((e >> 9) & 63u);
        int pb   = (int)(e >> 15);
        float dep = g_depth[pb*DDc + d];
        const float* fp = g_feat + (size_t)pb*CCc;
        float f0 = fp[lane];
        float f1 = fp[lane + 32];
        atomicAdd(&s[cell*CPAD + lane],      dep*f0);
        atomicAdd(&s[cell*CPAD + lane + 32], dep*f1);
    }
    __syncthreads();

    // ---- write-out: warp owns 4 (c,row) pairs; lanes walk consecutive iy.
    //      All offsets are compile-time immediates: ~2 instr per element.
    //      LDS lane stride = CPAD=65 words -> bank stride 1 (conflict-free); STG coalesced.
    #pragma unroll
    for (int pp = 0; pp < 4; ++pp) {
        int pr  = wid*4 + pp;
        int c   = pr >> 1;
        int row = pr & 1;
        const float* sp = s + (row*NYc + lane)*CPAD + c;
        float* op = out + (size_t)b*GRID_PER_B
                        + ((size_t)c*NXc + tix*TROWS + row)*NYc + lane;
        #pragma unroll
        for (int kk = 0; kk < 6; ++kk)
            op[kk*32] = sp[kk*32*CPAD];
        if (lane < 8)                      // 200 = 6*32 + 8
            op[6*32] = sp[6*32*CPAD];
    }
}

// ---------------- launch ----------------
extern "C" void kernel_launch(void* const* d_in, const int* in_sizes, int n_in,
                              void* d_out, int out_size) {
    const float* x     = (const float*)d_in[0];
    const float* rots  = (const float*)d_in[1];
    const float* trans = (const float*)d_in[2];
    const float* intr  = (const float*)d_in[3];
    const float* cw    = (const float*)d_in[4];
    const float* cb    = (const float*)d_in[5];
    float* out = (float*)d_out;

    static void* bincnt_ptr = nullptr;
    static cudaStream_t s2 = nullptr;
    static cudaEvent_t evA = nullptr, evB = nullptr;
    if (!bincnt_ptr) {
        cudaFuncSetAttribute(k_tile, cudaFuncAttributeMaxDynamicSharedMemorySize,
                             TILE_FLOATS*sizeof(float));
        cudaGetSymbolAddress(&bincnt_ptr, g_bincnt);
        cudaStreamCreateWithFlags(&s2, cudaStreamNonBlocking);
        cudaEventCreateWithFlags(&evA, cudaEventDisableTiming);
        cudaEventCreateWithFlags(&evB, cudaEventDisableTiming);
    }

    cudaMemsetAsync(bincnt_ptr, 0, NTILES*sizeof(int), 0);
    cudaEventRecord(evA, 0);

    // side stream: binning (independent of conv/softmax)
    cudaStreamWaitEvent(s2, evA, 0);
    k_bin<<<NPTS/256, 256, 0, s2>>>(rots, intr, trans);
    cudaEventRecord(evB, s2);

    // main stream: conv + softmax
    k_conv   <<<BN*KSP, 162>>>(x, cw);
    k_softmax<<<(BN*PXc)/4, 128>>>(cb, out + FINAL_ELEMS);

    // join, then tile accumulation
    cudaStreamWaitEvent(0, evB, 0);
    k_tile<<<NTILES, 1024, TILE_FLOATS*sizeof(float)>>>(out);
}